// round 14
// baseline (speedup 1.0000x reference)
#include <cuda_runtime.h>
#include <cuda_bf16.h>
#include <math.h>

#define EPSC 1e-6f
#define INV_SQRT_2PI 0.3989422804014327f

// deduped gamma tables (values within 4e-6 merged; weights preserve the mean)
__constant__ float GTU[5] = {0.715951561820333f, 1.039358092507381f, 0.948607106485449f,
                             0.484068718800797f, 1.446433070133343f};
__constant__ float WTU[5] = {4.f, 3.f, 1.f, 1.f, 1.f};
__constant__ float GSU[5] = {0.519483084417772f, 0.357944855434941f, 0.723301195883257f,
                             0.474918009444542f, 0.242049896394596f};
__constant__ float WSU[5] = {3.f, 4.f, 1.f, 1.f, 1.f};

// lower-triangle tile-pair tables for build_H (row tile >= col tile)
__constant__ int RT[10] = {0, 1, 1, 2, 2, 2, 3, 3, 3, 3};
__constant__ int CT[10] = {0, 0, 1, 0, 1, 2, 0, 1, 2, 3};

// ------------------- scratch (__device__ globals, no allocs) -------------------
__device__ float g_h1[64 * 512];
__device__ float g_zvar[64 * 64];
__device__ float g_a0[64 * 512];
__device__ float g_a1[64 * 512];
__device__ float g_a2[64 * 512];
__device__ float g_a3[64 * 512];
__device__ float g_v[64 * 512];
__device__ __nv_bfloat16 g_Hbf[(size_t)64 * 512 * 512];   // G = lower(H)+half-diag, bf16
__device__ __nv_bfloat16 g_w41bf[784 * 512];
__device__ float g_m41[64 * 784];

// ------------------- mma/ldmatrix helpers --------------------------------------
__device__ __forceinline__ void mma_bf16(float* d, unsigned a0, unsigned a1,
                                         unsigned a2, unsigned a3,
                                         unsigned b0, unsigned b1) {
    asm volatile(
        "mma.sync.aligned.m16n8k16.row.col.f32.bf16.bf16.f32 "
        "{%0,%1,%2,%3}, {%4,%5,%6,%7}, {%8,%9}, {%0,%1,%2,%3};"
        : "+f"(d[0]), "+f"(d[1]), "+f"(d[2]), "+f"(d[3])
        : "r"(a0), "r"(a1), "r"(a2), "r"(a3), "r"(b0), "r"(b1));
}
__device__ __forceinline__ void ldmx4(unsigned& r0, unsigned& r1, unsigned& r2,
                                      unsigned& r3, unsigned addr) {
    asm volatile(
        "ldmatrix.sync.aligned.m8n8.x4.shared.b16 {%0,%1,%2,%3}, [%4];"
        : "=r"(r0), "=r"(r1), "=r"(r2), "=r"(r3) : "r"(addr));
}

// ------------------- 8x4 warp-tile fp32 GEMM body ------------------------------
template <bool TANH>
__device__ __forceinline__ void warp_gemm_8x4(
    const float* __restrict__ A, int lda,
    const float* __restrict__ B, int ldb,
    const float* __restrict__ bias,
    float* __restrict__ out, int ldo,
    int m0, int n0, int K4, int lane)
{
    float s[8][4];
#pragma unroll
    for (int r = 0; r < 8; r++)
#pragma unroll
        for (int c = 0; c < 4; c++) s[r][c] = 0.f;

    const float4* ap[8];
#pragma unroll
    for (int r = 0; r < 8; r++)
        ap[r] = reinterpret_cast<const float4*>(A + (size_t)(m0 + r) * lda);
    const float4* bp[4];
#pragma unroll
    for (int c = 0; c < 4; c++)
        bp[c] = reinterpret_cast<const float4*>(B + (size_t)(n0 + c) * ldb);

    for (int i = lane; i < K4; i += 32) {
        float4 w[4];
#pragma unroll
        for (int c = 0; c < 4; c++) w[c] = bp[c][i];
#pragma unroll
        for (int r = 0; r < 8; r++) {
            float4 a = ap[r][i];
#pragma unroll
            for (int c = 0; c < 4; c++)
                s[r][c] += a.x * w[c].x + a.y * w[c].y + a.z * w[c].z + a.w * w[c].w;
        }
    }
#pragma unroll
    for (int off = 16; off; off >>= 1)
#pragma unroll
        for (int r = 0; r < 8; r++)
#pragma unroll
            for (int c = 0; c < 4; c++)
                s[r][c] += __shfl_xor_sync(0xffffffff, s[r][c], off);

    if (lane < 8) {
        float4 bb = *reinterpret_cast<const float4*>(bias + n0);
        float v0 = 0.f, v1 = 0.f, v2 = 0.f, v3 = 0.f;
#pragma unroll
        for (int r = 0; r < 8; r++)
            if (lane == r) { v0 = s[r][0]; v1 = s[r][1]; v2 = s[r][2]; v3 = s[r][3]; }
        float4 o;
        if (TANH) {
            o.x = tanhf(v0 + bb.x); o.y = tanhf(v1 + bb.y);
            o.z = tanhf(v2 + bb.z); o.w = tanhf(v3 + bb.w);
        } else {
            o.x = v0 + bb.x; o.y = v1 + bb.y; o.z = v2 + bb.z; o.w = v3 + bb.w;
        }
        *reinterpret_cast<float4*>(out + (size_t)(m0 + lane) * ldo + n0) = o;
    }
}

// ------------------- h1 GEMM (8x4 tiles) + w41 bf16 conversion -----------------
__global__ __launch_bounds__(256) void h1_conv(
    const float* __restrict__ x, const float* __restrict__ w1,
    const float* __restrict__ b1, const float* __restrict__ w41)
{
    if (blockIdx.x >= 128) {           // w41 -> bf16, 784 blocks
        int i = (blockIdx.x - 128) * 256 + threadIdx.x;
        float2 v = reinterpret_cast<const float2*>(w41)[i];
        reinterpret_cast<__nv_bfloat162*>(g_w41bf)[i] = __floats2bfloat162_rn(v.x, v.y);
        return;
    }
    const int wid  = (blockIdx.x * 256 + threadIdx.x) >> 5;
    const int lane = threadIdx.x & 31;
    const int tm = wid >> 7, tn = wid & 127;
    warp_gemm_8x4<true>(x, 784, w1, 784, b1, g_h1, 512,
                        tm * 8, tn * 4, 196, lane);
}

// ------------------- zmoments: z GEMMs + tanh moment coefficients --------------
__global__ __launch_bounds__(256) void zmoments(
    const float* __restrict__ h1,
    const float* __restrict__ w21, const float* __restrict__ b21,
    const float* __restrict__ w22, const float* __restrict__ b22,
    const float* __restrict__ w3, const float* __restrict__ b3,
    float* __restrict__ out)
{
    __shared__ float hs[512];
    __shared__ float zm[64], zr[64];
    const int t = threadIdx.x;
    const int b = blockIdx.x >> 1;
    const int half = blockIdx.x & 1;
    const int lane = t & 31, w = t >> 5;

    if (t < 128)
        *reinterpret_cast<float4*>(&hs[t * 4]) =
            *reinterpret_cast<const float4*>(h1 + (size_t)b * 512 + t * 4);
    __syncthreads();

#pragma unroll
    for (int u = 0; u < 8; u++) {
        int n = w * 8 + u;
        const float4* wmp = reinterpret_cast<const float4*>(w21 + (size_t)n * 512);
        const float4* wlp = reinterpret_cast<const float4*>(w22 + (size_t)n * 512);
        float sm = 0.f, sl = 0.f;
#pragma unroll
        for (int i = lane; i < 128; i += 32) {
            float4 hv = *reinterpret_cast<const float4*>(&hs[i * 4]);
            float4 a = wmp[i], bb2 = wlp[i];
            sm += hv.x * a.x + hv.y * a.y + hv.z * a.z + hv.w * a.w;
            sl += hv.x * bb2.x + hv.y * bb2.y + hv.z * bb2.z + hv.w * bb2.w;
        }
#pragma unroll
        for (int off = 16; off; off >>= 1) {
            sm += __shfl_xor_sync(0xffffffff, sm, off);
            sl += __shfl_xor_sync(0xffffffff, sl, off);
        }
        if (lane == 0) {
            sm += b21[n]; sl += b22[n];
            float ev = expf(sl);
            zm[n] = sm; zr[n] = ev;
            if (half == 0) {
                out[b * 64 + n] = sm;                  // z_mean
            } else {
                out[64 * 64 + b * 64 + n] = sl;        // z_logvar
                g_zvar[b * 64 + n] = ev;
            }
        }
    }
    __syncthreads();

    const int i = (half << 8) + t;
    const float4* wr = reinterpret_cast<const float4*>(w3 + (size_t)i * 64);
    float v = 0.f, m = b3[i];
#pragma unroll
    for (int q = 0; q < 16; q++) {
        float4 wv = wr[q];
        v += wv.x * wv.x * zr[q * 4 + 0] + wv.y * wv.y * zr[q * 4 + 1]
           + wv.z * wv.z * zr[q * 4 + 2] + wv.w * wv.w * zr[q * 4 + 3];
        m += wv.x * zm[q * 4 + 0] + wv.y * zm[q * 4 + 1]
           + wv.z * zm[q * 4 + 2] + wv.w * zm[q * 4 + 3];
    }
    v = fmaxf(v, EPSC);

    float s0 = 0.f, s1 = 0.f, s2 = 0.f, s3 = 0.f;
#pragma unroll
    for (int g = 0; g < 5; g++) {
        float gam = GTU[g], wgt = WTU[g];
        float cg = 1.0f / (2.0f * gam * gam);
        float ivh = v + cg;
        float sq = sqrtf(ivh);
        float mu = m / sq;
        float Bv = expf(-0.5f * mu * mu) * INV_SQRT_2PI / sq;
        float Cv = 0.5f * (1.0f + erff(mu * 0.70710678118654752f));
        s0 += wgt * (2.f * Cv - 1.f);
        s1 += wgt * (2.f * Bv);
        s2 += wgt * (-Bv * m / ivh);
        s3 += wgt * ((1.f / 3.f) * Bv * (m * m - ivh) / (ivh * ivh));
    }
    int idx = b * 512 + i;
    g_a0[idx] = s0 * 0.1f;
    g_a1[idx] = s1 * 0.1f;
    g_a2[idx] = s2 * 0.1f;
    g_a3[idx] = s3 * 0.1f;
    g_v[idx]  = v;
}

// ------------------- build G (bf16 MMA) + m41 GEMM (merged launch) -------------
__global__ __launch_bounds__(256, 2) void build_H_m41(
    const float* __restrict__ w3, const float* __restrict__ w41,
    const float* __restrict__ b41)
{
    __shared__ __align__(16) char sbuf[36864];   // Abf+Bbf during MMA; Gt after
    __shared__ float zrs[64];
    __shared__ float cA1i[128], cA2i[128], cA3i[128], cVi[128];
    __shared__ float cA1j[128], cA2j[128], cA3j[128], cVj[128];

    const int t = threadIdx.x;
    if (blockIdx.x >= 640) {            // ---- m41 8x4 warp GEMM ----
        const int wid  = ((blockIdx.x - 640) * 256 + t) >> 5;
        const int lane = t & 31;
        const int tm = wid / 196, tn = wid - tm * 196;
        warp_gemm_8x4<false>(g_a0, 512, w41, 512, b41, g_m41, 784,
                             tm * 8, tn * 4, 128, lane);
        return;
    }

    __nv_bfloat16 (*Abf)[72] = reinterpret_cast<__nv_bfloat16(*)[72]>(sbuf);
    __nv_bfloat16 (*Bbf)[72] = reinterpret_cast<__nv_bfloat16(*)[72]>(sbuf + 18432);

    const int pair = blockIdx.x % 10;
    const int b = blockIdx.x / 10;
    const int ib = RT[pair] * 128, jb = CT[pair] * 128;
    const bool diag_tile = (ib == jb);

    if (t < 64) zrs[t] = g_zvar[b * 64 + t];
    {   // coalesced coefficient staging
        int side = t >> 7;
        int r = t & 127;
        int gg = b * 512 + (side ? jb : ib) + r;
        if (side == 0) {
            cA1i[r] = g_a1[gg]; cA2i[r] = g_a2[gg];
            cA3i[r] = g_a3[gg]; cVi[r]  = g_v[gg];
        } else {
            cA1j[r] = g_a1[gg]; cA2j[r] = g_a2[gg];
            cA3j[r] = g_a3[gg]; cVj[r]  = g_v[gg];
        }
    }
    __syncthreads();

    {   // stage W3 tiles (bf16), B side z-scaled
        int row = t >> 1, base = (t & 1) * 8;
        const float4* wa = reinterpret_cast<const float4*>(w3 + (size_t)(ib + row) * 64);
        const float4* wb = reinterpret_cast<const float4*>(w3 + (size_t)(jb + row) * 64);
#pragma unroll
        for (int q = 0; q < 8; q++) {
            int c4 = base + q;
            float4 va = wa[c4];
            *reinterpret_cast<__nv_bfloat162*>(&Abf[row][c4 * 4])     = __floats2bfloat162_rn(va.x, va.y);
            *reinterpret_cast<__nv_bfloat162*>(&Abf[row][c4 * 4 + 2]) = __floats2bfloat162_rn(va.z, va.w);
            float4 vb = wb[c4];
            *reinterpret_cast<__nv_bfloat162*>(&Bbf[row][c4 * 4])     =
                __floats2bfloat162_rn(vb.x * zrs[c4 * 4 + 0], vb.y * zrs[c4 * 4 + 1]);
            *reinterpret_cast<__nv_bfloat162*>(&Bbf[row][c4 * 4 + 2]) =
                __floats2bfloat162_rn(vb.z * zrs[c4 * 4 + 2], vb.w * zrs[c4 * 4 + 3]);
        }
    }
    __syncthreads();

    const int lane = t & 31;
    const int w = t >> 5;
    const int wm = w & 3, wn = w >> 2;
    const int grp = lane >> 2, qid = lane & 3;

    unsigned as_base = (unsigned)__cvta_generic_to_shared(&Abf[0][0]);
    unsigned bs_base = (unsigned)__cvta_generic_to_shared(&Bbf[0][0]);
    unsigned a_addr = as_base + (((wm * 32 + (lane & 15)) * 72 + ((lane >> 4) << 3)) << 1);
    unsigned b_addr = bs_base + (((wn * 64 + (lane & 7) + ((lane & 16) >> 1)) * 72 + (lane & 8)) << 1);

    float d[2][8][4];
#pragma unroll
    for (int mt = 0; mt < 2; mt++)
#pragma unroll
        for (int nt = 0; nt < 8; nt++)
#pragma unroll
            for (int e = 0; e < 4; e++) d[mt][nt][e] = 0.f;

#pragma unroll
    for (int kk = 0; kk < 4; kk++) {
        unsigned a[2][4];
        ldmx4(a[0][0], a[0][1], a[0][2], a[0][3], a_addr + kk * 32);
        ldmx4(a[1][0], a[1][1], a[1][2], a[1][3], a_addr + 2304 + kk * 32);
#pragma unroll
        for (int np = 0; np < 4; np++) {
            unsigned b0, b1, b2, b3;
            ldmx4(b0, b1, b2, b3, b_addr + np * 2304 + kk * 32);
            mma_bf16(d[0][2 * np],     a[0][0], a[0][1], a[0][2], a[0][3], b0, b1);
            mma_bf16(d[0][2 * np + 1], a[0][0], a[0][1], a[0][2], a[0][3], b2, b3);
            mma_bf16(d[1][2 * np],     a[1][0], a[1][1], a[1][2], a[1][3], b0, b1);
            mma_bf16(d[1][2 * np + 1], a[1][0], a[1][1], a[1][2], a[1][3], b2, b3);
        }
    }
    __syncthreads();   // ldmx4 done -> safe to overlay Gt on Abf/Bbf

    __nv_bfloat16 (*Gt)[136] = reinterpret_cast<__nv_bfloat16(*)[136]>(sbuf);
#pragma unroll
    for (int nt = 0; nt < 8; nt++) {
        int jl0 = wn * 64 + nt * 8 + qid * 2;
        float A1j[2] = {cA1j[jl0], cA1j[jl0 + 1]};
        float A2j[2] = {cA2j[jl0], cA2j[jl0 + 1]};
        float A3j[2] = {cA3j[jl0], cA3j[jl0 + 1]};
        float Vj[2]  = {cVj[jl0],  cVj[jl0 + 1]};
#pragma unroll
        for (int mh = 0; mh < 4; mh++) {
            int mt = mh >> 1, hh = mh & 1;
            int il = wm * 32 + mt * 16 + grp + hh * 8;
            int gi = ib + il;
            float A1 = cA1i[il], A2 = cA2i[il], A3 = cA3i[il], Vv = cVi[il];
            float hv[2];
#pragma unroll
            for (int c = 0; c < 2; c++) {
                int gj = jb + jl0 + c;
                float c0 = d[mt][nt][hh * 2 + c];
                float h;
                if (diag_tile && gi < gj) {
                    h = 0.f;
                } else if (gi == gj) {
                    c0 = Vv;                           // exact fp32 diagonal
                    float cc2 = c0 * c0;
                    h = 0.5f * (A1 * A1j[c] * c0
                              + 2.f * A2 * A2j[c] * cc2
                              + A3 * A3j[c] * (6.f * cc2 * c0 + 9.f * Vv * Vj[c] * c0));
                } else {
                    float cc2 = c0 * c0;
                    h = A1 * A1j[c] * c0
                      + 2.f * A2 * A2j[c] * cc2
                      + A3 * A3j[c] * (6.f * cc2 * c0 + 9.f * Vv * Vj[c] * c0);
                }
                hv[c] = h;
            }
            *reinterpret_cast<__nv_bfloat162*>(&Gt[il][jl0]) =
                __floats2bfloat162_rn(hv[0], hv[1]);
        }
    }
    __syncthreads();

#pragma unroll
    for (int q = 0; q < 8; q++) {
        int f = t + q * 256;
        int row = f >> 4, c16 = f & 15;
        *reinterpret_cast<uint4*>(
            &g_Hbf[((size_t)b * 512 + ib + row) * 512 + jb + c16 * 8]) =
            *reinterpret_cast<const uint4*>(&Gt[row][c16 * 8]);
    }
}

// ------------------- diag + probs: batch-paired bf16 MMA, cp.async x2 ----------
// Block: 128 o-rows x 2 batches, 512 threads (16 warps = 4 o x 2 j x 2 batch).
// smem stage: [A 18432][B(b0) 18432][B(b1) 18432] = 55296 B; two stages.
#define BSTG 55296u
__global__ __launch_bounds__(512, 1) void bilinear_probs_bf16(
    const float* __restrict__ w41, float* __restrict__ probs_out)
{
    extern __shared__ __align__(16) char dsm[];
    __shared__ float red[2][2][128];

    const int t = threadIdx.x;
    const int lane = t & 31;
    const int w = t >> 5;              // 0..15
    const int wb  = w >> 3;            // batch select
    const int wm2 = w & 3;             // o-group (32 rows)
    const int wj  = (w >> 2) & 1;      // j-half (64 cols)
    const int ob = blockIdx.x * 128;
    const int b0 = blockIdx.y * 2;
    const __nv_bfloat16* Hp[2] = {g_Hbf + ((size_t)b0 << 18),
                                  g_Hbf + ((size_t)(b0 + 1) << 18)};

    const int grp = lane >> 2;
    const int qid = lane & 3;

    unsigned smem_base = (unsigned)__cvta_generic_to_shared(dsm);
    unsigned a_frag = smem_base +
        (((wm2 * 32 + (lane & 15)) * 72 + ((lane >> 4) << 3)) << 1);
    unsigned b_frag = smem_base + 18432u + (unsigned)wb * 18432u +
        (((wj * 64 + (lane & 7) + ((lane & 16) >> 1)) * 72 + (lane & 8)) << 1);

    float s[2][2];                     // partials: [mt][half-row]
    s[0][0] = s[0][1] = s[1][0] = s[1][1] = 0.f;

    for (int jt = 0; jt < 4; jt++) {
        const int jb = jt * 128;
        const int nch = 2 * (jt + 1);  // 64-wide k-chunks (triangular)
        float d[2][8][4];
#pragma unroll
        for (int mt = 0; mt < 2; mt++)
#pragma unroll
            for (int nt = 0; nt < 8; nt++)
#pragma unroll
                for (int c = 0; c < 4; c++) d[mt][nt][c] = 0.f;

        auto stage = [&](int kc, int buf) {
            unsigned off = buf ? BSTG : 0u;
#pragma unroll
            for (int q = 0; q < 2; q++) {          // A: 128 rows x 64 k (shared)
                int f = t + q * 512;
                int row = f >> 3, g = f & 7;
                int og = ob + row;
                const __nv_bfloat16* asrc =
                    g_w41bf + (size_t)(og < 784 ? og : 783) * 512 + kc + g * 8;
                unsigned adst = smem_base + off + ((unsigned)(row * 72 + g * 8) << 1);
                unsigned nbytes = (og < 784) ? 16u : 0u;   // zero-fill OOB rows
                asm volatile("cp.async.cg.shared.global [%0], [%1], 16, %2;"
                             :: "r"(adst), "l"(asrc), "r"(nbytes));
            }
#pragma unroll
            for (int wb2 = 0; wb2 < 2; wb2++)      // B: 2 batches x 128 rows x 64 k
#pragma unroll
                for (int q = 0; q < 2; q++) {
                    int f = t + q * 512;
                    int row = f >> 3, g = f & 7;
                    const __nv_bfloat16* bsrc =
                        Hp[wb2] + (size_t)(jb + row) * 512 + kc + g * 8;
                    unsigned bdst = smem_base + off + 18432u +
                        (unsigned)wb2 * 18432u + ((unsigned)(row * 72 + g * 8) << 1);
                    asm volatile("cp.async.cg.shared.global [%0], [%1], 16;"
                                 :: "r"(bdst), "l"(bsrc));
                }
            asm volatile("cp.async.commit_group;");
        };

        stage(0, 0);
        for (int c = 0; c < nch; c++) {
            if (c + 1 < nch) {
                stage((c + 1) * 64, (c + 1) & 1);
                asm volatile("cp.async.wait_group 1;" ::: "memory");
            } else {
                asm volatile("cp.async.wait_group 0;" ::: "memory");
            }
            __syncthreads();

            unsigned sel = (c & 1) ? BSTG : 0u;
#pragma unroll
            for (int kk = 0; kk < 4; kk++) {
                unsigned a[2][4];
                ldmx4(a[0][0], a[0][1], a[0][2], a[0][3], a_frag + sel + kk * 32);
                ldmx4(a[1][0], a[1][1], a[1][2], a[1][3], a_frag + sel + 2304 + kk * 32);
#pragma unroll
                for (int np = 0; np < 4; np++) {
                    unsigned b0r, b1r, b2r, b3r;
                    ldmx4(b0r, b1r, b2r, b3r, b_frag + sel + np * 2304 + kk * 32);
                    mma_bf16(d[0][2 * np],     a[0][0], a[0][1], a[0][2], a[0][3], b0r, b1r);
                    mma_bf16(d[0][2 * np + 1], a[0][0], a[0][1], a[0][2], a[0][3], b2r, b3r);
                    mma_bf16(d[1][2 * np],     a[1][0], a[1][1], a[1][2], a[1][3], b0r, b1r);
                    mma_bf16(d[1][2 * np + 1], a[1][0], a[1][1], a[1][2], a[1][3], b2r, b3r);
                }
            }
            __syncthreads();
        }

        // fold w41[o, j] for this warp's 64-wide j-slice
#pragma unroll
        for (int mt = 0; mt < 2; mt++) {
            int o0 = ob + wm2 * 32 + mt * 16 + grp;
#pragma unroll
            for (int hh = 0; hh < 2; hh++) {
                int og = o0 + hh * 8;
                if (og < 784) {
                    float acc = 0.f;
#pragma unroll
                    for (int nt = 0; nt < 8; nt++) {
                        int j0 = jb + wj * 64 + nt * 8 + qid * 2;
                        float2 u = *reinterpret_cast<const float2*>(
                            w41 + (size_t)og * 512 + j0);
                        acc += d[mt][nt][hh * 2] * u.x + d[mt][nt][hh * 2 + 1] * u.y;
                    }
                    s[mt][hh] += acc;
                }
            }
        }
    }

    // qid-shuffle reduce, then cross-warp (wj) reduce via smem
#pragma unroll
    for (int mt = 0; mt < 2; mt++)
#pragma unroll
        for (int hh = 0; hh < 2; hh++) {
            s[mt][hh] += __shfl_xor_sync(0xffffffff, s[mt][hh], 1);
            s[mt][hh] += __shfl_xor_sync(0xffffffff, s[mt][hh], 2);
        }
    if (qid == 0) {
#pragma unroll
        for (int mt = 0; mt < 2; mt++)
#pragma unroll
            for (int hh = 0; hh < 2; hh++)
                red[wb][wj][wm2 * 32 + mt * 16 + grp + hh * 8] = s[mt][hh];
    }
    __syncthreads();

    if (t < 256) {
        int wb3 = t >> 7, r = t & 127;
        int og = ob + r;
        if (og < 784) {
            float vv = fmaxf(2.f * (red[wb3][0][r] + red[wb3][1][r]), EPSC);
            float m = g_m41[(b0 + wb3) * 784 + og];
            float sacc = 0.f;
#pragma unroll
            for (int g = 0; g < 5; g++) {
                float gam = GSU[g];
                float cg = 1.0f / (2.0f * gam * gam);
                float ivh = vv + cg;
                sacc += WSU[g] * 0.5f * (1.0f + erff(m / sqrtf(2.0f * ivh)));
            }
            probs_out[(b0 + wb3) * 784 + og] = sacc * 0.1f;
        }
    }
}

// ------------------- launcher --------------------------------------------------
extern "C" void kernel_launch(void* const* d_in, const int* in_sizes, int n_in,
                              void* d_out, int out_size)
{
    const float* x   = (const float*)d_in[0];
    const float* w1  = (const float*)d_in[1];
    const float* b1  = (const float*)d_in[2];
    const float* w21 = (const float*)d_in[3];
    const float* b21 = (const float*)d_in[4];
    const float* w22 = (const float*)d_in[5];
    const float* b22 = (const float*)d_in[6];
    const float* w3  = (const float*)d_in[7];
    const float* b3  = (const float*)d_in[8];
    const float* w41 = (const float*)d_in[9];
    const float* b41 = (const float*)d_in[10];
    float* out = (float*)d_out;

    float* h1;
    cudaGetSymbolAddress((void**)&h1, g_h1);

    const int BIL_SMEM = 2 * 55296;    // two stages, batch-paired
    cudaFuncSetAttribute(bilinear_probs_bf16,
                         cudaFuncAttributeMaxDynamicSharedMemorySize, BIL_SMEM);

    // h1 GEMM (128 blocks, 8x4 warp tiles) + w41 bf16 conversion (784 blocks)
    h1_conv<<<912, 256>>>(x, w1, b1, w41);
    // z GEMMs + tanh moment coefficients, one launch (z_mean/z_logvar -> out)
    zmoments<<<128, 256>>>(h1, w21, b21, w22, b22, w3, b3, out);
    // G build via bf16 MMA (640 blocks) + m41 GEMM (196 blocks, 8x4 tiles)
    build_H_m41<<<836, 256>>>(w3, w41, b41);
    // diag of cov41 (batch-paired, double-buffered cp.async) + fused probs
    bilinear_probs_bf16<<<dim3(7, 32), 512, BIL_SMEM>>>(w41, out + 2 * 64 * 64);
}

// round 16
// speedup vs baseline: 1.0760x; 1.0760x over previous
#include <cuda_runtime.h>
#include <cuda_bf16.h>
#include <math.h>

#define EPSC 1e-6f
#define INV_SQRT_2PI 0.3989422804014327f

// deduped gamma tables (values within 4e-6 merged; weights preserve the mean)
__constant__ float GTU[5] = {0.715951561820333f, 1.039358092507381f, 0.948607106485449f,
                             0.484068718800797f, 1.446433070133343f};
__constant__ float WTU[5] = {4.f, 3.f, 1.f, 1.f, 1.f};
__constant__ float GSU[5] = {0.519483084417772f, 0.357944855434941f, 0.723301195883257f,
                             0.474918009444542f, 0.242049896394596f};
__constant__ float WSU[5] = {3.f, 4.f, 1.f, 1.f, 1.f};

// lower-triangle tile-pair tables for build_H (row tile >= col tile)
__constant__ int RT[10] = {0, 1, 1, 2, 2, 2, 3, 3, 3, 3};
__constant__ int CT[10] = {0, 0, 1, 0, 1, 2, 0, 1, 2, 3};

// ------------------- scratch (__device__ globals, no allocs) -------------------
__device__ float g_h1[64 * 512];
__device__ float g_zvar[64 * 64];
__device__ float g_a0[64 * 512];
__device__ float g_a1[64 * 512];
__device__ float g_a2[64 * 512];
__device__ float g_a3[64 * 512];
__device__ float g_v[64 * 512];
__device__ __nv_bfloat16 g_Hbf[(size_t)64 * 512 * 512];   // G = lower(H)+half-diag, bf16
__device__ __nv_bfloat16 g_w41bf[784 * 512];
__device__ float g_m41[64 * 784];

// ------------------- mma/ldmatrix helpers --------------------------------------
__device__ __forceinline__ void mma_bf16(float* d, unsigned a0, unsigned a1,
                                         unsigned a2, unsigned a3,
                                         unsigned b0, unsigned b1) {
    asm volatile(
        "mma.sync.aligned.m16n8k16.row.col.f32.bf16.bf16.f32 "
        "{%0,%1,%2,%3}, {%4,%5,%6,%7}, {%8,%9}, {%0,%1,%2,%3};"
        : "+f"(d[0]), "+f"(d[1]), "+f"(d[2]), "+f"(d[3])
        : "r"(a0), "r"(a1), "r"(a2), "r"(a3), "r"(b0), "r"(b1));
}
__device__ __forceinline__ void ldmx4(unsigned& r0, unsigned& r1, unsigned& r2,
                                      unsigned& r3, unsigned addr) {
    asm volatile(
        "ldmatrix.sync.aligned.m8n8.x4.shared.b16 {%0,%1,%2,%3}, [%4];"
        : "=r"(r0), "=r"(r1), "=r"(r2), "=r"(r3) : "r"(addr));
}

// ------------------- 8x4 warp-tile fp32 GEMM body ------------------------------
template <bool TANH>
__device__ __forceinline__ void warp_gemm_8x4(
    const float* __restrict__ A, int lda,
    const float* __restrict__ B, int ldb,
    const float* __restrict__ bias,
    float* __restrict__ out, int ldo,
    int m0, int n0, int K4, int lane)
{
    float s[8][4];
#pragma unroll
    for (int r = 0; r < 8; r++)
#pragma unroll
        for (int c = 0; c < 4; c++) s[r][c] = 0.f;

    const float4* ap[8];
#pragma unroll
    for (int r = 0; r < 8; r++)
        ap[r] = reinterpret_cast<const float4*>(A + (size_t)(m0 + r) * lda);
    const float4* bp[4];
#pragma unroll
    for (int c = 0; c < 4; c++)
        bp[c] = reinterpret_cast<const float4*>(B + (size_t)(n0 + c) * ldb);

    for (int i = lane; i < K4; i += 32) {
        float4 w[4];
#pragma unroll
        for (int c = 0; c < 4; c++) w[c] = bp[c][i];
#pragma unroll
        for (int r = 0; r < 8; r++) {
            float4 a = ap[r][i];
#pragma unroll
            for (int c = 0; c < 4; c++)
                s[r][c] += a.x * w[c].x + a.y * w[c].y + a.z * w[c].z + a.w * w[c].w;
        }
    }
#pragma unroll
    for (int off = 16; off; off >>= 1)
#pragma unroll
        for (int r = 0; r < 8; r++)
#pragma unroll
            for (int c = 0; c < 4; c++)
                s[r][c] += __shfl_xor_sync(0xffffffff, s[r][c], off);

    if (lane < 8) {
        float4 bb = *reinterpret_cast<const float4*>(bias + n0);
        float v0 = 0.f, v1 = 0.f, v2 = 0.f, v3 = 0.f;
#pragma unroll
        for (int r = 0; r < 8; r++)
            if (lane == r) { v0 = s[r][0]; v1 = s[r][1]; v2 = s[r][2]; v3 = s[r][3]; }
        float4 o;
        if (TANH) {
            o.x = tanhf(v0 + bb.x); o.y = tanhf(v1 + bb.y);
            o.z = tanhf(v2 + bb.z); o.w = tanhf(v3 + bb.w);
        } else {
            o.x = v0 + bb.x; o.y = v1 + bb.y; o.z = v2 + bb.z; o.w = v3 + bb.w;
        }
        *reinterpret_cast<float4*>(out + (size_t)(m0 + lane) * ldo + n0) = o;
    }
}

// ------------------- h1 GEMM (8x4 tiles) + w41 bf16 conversion -----------------
__global__ __launch_bounds__(256) void h1_conv(
    const float* __restrict__ x, const float* __restrict__ w1,
    const float* __restrict__ b1, const float* __restrict__ w41)
{
    if (blockIdx.x >= 128) {           // w41 -> bf16, 784 blocks
        int i = (blockIdx.x - 128) * 256 + threadIdx.x;
        float2 v = reinterpret_cast<const float2*>(w41)[i];
        reinterpret_cast<__nv_bfloat162*>(g_w41bf)[i] = __floats2bfloat162_rn(v.x, v.y);
        return;
    }
    const int wid  = (blockIdx.x * 256 + threadIdx.x) >> 5;
    const int lane = threadIdx.x & 31;
    const int tm = wid >> 7, tn = wid & 127;
    warp_gemm_8x4<true>(x, 784, w1, 784, b1, g_h1, 512,
                        tm * 8, tn * 4, 196, lane);
}

// ------------------- zmoments: z GEMMs + tanh moment coefficients --------------
__global__ __launch_bounds__(256) void zmoments(
    const float* __restrict__ h1,
    const float* __restrict__ w21, const float* __restrict__ b21,
    const float* __restrict__ w22, const float* __restrict__ b22,
    const float* __restrict__ w3, const float* __restrict__ b3,
    float* __restrict__ out)
{
    __shared__ float hs[512];
    __shared__ float zm[64], zr[64];
    const int t = threadIdx.x;
    const int b = blockIdx.x >> 1;
    const int half = blockIdx.x & 1;
    const int lane = t & 31, w = t >> 5;

    if (t < 128)
        *reinterpret_cast<float4*>(&hs[t * 4]) =
            *reinterpret_cast<const float4*>(h1 + (size_t)b * 512 + t * 4);
    __syncthreads();

#pragma unroll
    for (int u = 0; u < 8; u++) {
        int n = w * 8 + u;
        const float4* wmp = reinterpret_cast<const float4*>(w21 + (size_t)n * 512);
        const float4* wlp = reinterpret_cast<const float4*>(w22 + (size_t)n * 512);
        float sm = 0.f, sl = 0.f;
#pragma unroll
        for (int i = lane; i < 128; i += 32) {
            float4 hv = *reinterpret_cast<const float4*>(&hs[i * 4]);
            float4 a = wmp[i], bb2 = wlp[i];
            sm += hv.x * a.x + hv.y * a.y + hv.z * a.z + hv.w * a.w;
            sl += hv.x * bb2.x + hv.y * bb2.y + hv.z * bb2.z + hv.w * bb2.w;
        }
#pragma unroll
        for (int off = 16; off; off >>= 1) {
            sm += __shfl_xor_sync(0xffffffff, sm, off);
            sl += __shfl_xor_sync(0xffffffff, sl, off);
        }
        if (lane == 0) {
            sm += b21[n]; sl += b22[n];
            float ev = expf(sl);
            zm[n] = sm; zr[n] = ev;
            if (half == 0) {
                out[b * 64 + n] = sm;                  // z_mean
            } else {
                out[64 * 64 + b * 64 + n] = sl;        // z_logvar
                g_zvar[b * 64 + n] = ev;
            }
        }
    }
    __syncthreads();

    const int i = (half << 8) + t;
    const float4* wr = reinterpret_cast<const float4*>(w3 + (size_t)i * 64);
    float v = 0.f, m = b3[i];
#pragma unroll
    for (int q = 0; q < 16; q++) {
        float4 wv = wr[q];
        v += wv.x * wv.x * zr[q * 4 + 0] + wv.y * wv.y * zr[q * 4 + 1]
           + wv.z * wv.z * zr[q * 4 + 2] + wv.w * wv.w * zr[q * 4 + 3];
        m += wv.x * zm[q * 4 + 0] + wv.y * zm[q * 4 + 1]
           + wv.z * zm[q * 4 + 2] + wv.w * zm[q * 4 + 3];
    }
    v = fmaxf(v, EPSC);

    float s0 = 0.f, s1 = 0.f, s2 = 0.f, s3 = 0.f;
#pragma unroll
    for (int g = 0; g < 5; g++) {
        float gam = GTU[g], wgt = WTU[g];
        float cg = 1.0f / (2.0f * gam * gam);
        float ivh = v + cg;
        float sq = sqrtf(ivh);
        float mu = m / sq;
        float Bv = expf(-0.5f * mu * mu) * INV_SQRT_2PI / sq;
        float Cv = 0.5f * (1.0f + erff(mu * 0.70710678118654752f));
        s0 += wgt * (2.f * Cv - 1.f);
        s1 += wgt * (2.f * Bv);
        s2 += wgt * (-Bv * m / ivh);
        s3 += wgt * ((1.f / 3.f) * Bv * (m * m - ivh) / (ivh * ivh));
    }
    int idx = b * 512 + i;
    g_a0[idx] = s0 * 0.1f;
    g_a1[idx] = s1 * 0.1f;
    g_a2[idx] = s2 * 0.1f;
    g_a3[idx] = s3 * 0.1f;
    g_v[idx]  = v;
}

// ------------------- build G (bf16 MMA) + m41 GEMM (merged launch) -------------
__global__ __launch_bounds__(256, 2) void build_H_m41(
    const float* __restrict__ w3, const float* __restrict__ w41,
    const float* __restrict__ b41)
{
    __shared__ __align__(16) char sbuf[36864];   // Abf+Bbf during MMA; Gt after
    __shared__ float zrs[64];
    __shared__ float cA1i[128], cA2i[128], cA3i[128], cVi[128];
    __shared__ float cA1j[128], cA2j[128], cA3j[128], cVj[128];

    const int t = threadIdx.x;
    if (blockIdx.x >= 640) {            // ---- m41 8x4 warp GEMM ----
        const int wid  = ((blockIdx.x - 640) * 256 + t) >> 5;
        const int lane = t & 31;
        const int tm = wid / 196, tn = wid - tm * 196;
        warp_gemm_8x4<false>(g_a0, 512, w41, 512, b41, g_m41, 784,
                             tm * 8, tn * 4, 128, lane);
        return;
    }

    __nv_bfloat16 (*Abf)[72] = reinterpret_cast<__nv_bfloat16(*)[72]>(sbuf);
    __nv_bfloat16 (*Bbf)[72] = reinterpret_cast<__nv_bfloat16(*)[72]>(sbuf + 18432);

    const int pair = blockIdx.x % 10;
    const int b = blockIdx.x / 10;
    const int ib = RT[pair] * 128, jb = CT[pair] * 128;
    const bool diag_tile = (ib == jb);

    if (t < 64) zrs[t] = g_zvar[b * 64 + t];
    {   // coalesced coefficient staging
        int side = t >> 7;
        int r = t & 127;
        int gg = b * 512 + (side ? jb : ib) + r;
        if (side == 0) {
            cA1i[r] = g_a1[gg]; cA2i[r] = g_a2[gg];
            cA3i[r] = g_a3[gg]; cVi[r]  = g_v[gg];
        } else {
            cA1j[r] = g_a1[gg]; cA2j[r] = g_a2[gg];
            cA3j[r] = g_a3[gg]; cVj[r]  = g_v[gg];
        }
    }
    __syncthreads();

    {   // stage W3 tiles (bf16), B side z-scaled
        int row = t >> 1, base = (t & 1) * 8;
        const float4* wa = reinterpret_cast<const float4*>(w3 + (size_t)(ib + row) * 64);
        const float4* wb = reinterpret_cast<const float4*>(w3 + (size_t)(jb + row) * 64);
#pragma unroll
        for (int q = 0; q < 8; q++) {
            int c4 = base + q;
            float4 va = wa[c4];
            *reinterpret_cast<__nv_bfloat162*>(&Abf[row][c4 * 4])     = __floats2bfloat162_rn(va.x, va.y);
            *reinterpret_cast<__nv_bfloat162*>(&Abf[row][c4 * 4 + 2]) = __floats2bfloat162_rn(va.z, va.w);
            float4 vb = wb[c4];
            *reinterpret_cast<__nv_bfloat162*>(&Bbf[row][c4 * 4])     =
                __floats2bfloat162_rn(vb.x * zrs[c4 * 4 + 0], vb.y * zrs[c4 * 4 + 1]);
            *reinterpret_cast<__nv_bfloat162*>(&Bbf[row][c4 * 4 + 2]) =
                __floats2bfloat162_rn(vb.z * zrs[c4 * 4 + 2], vb.w * zrs[c4 * 4 + 3]);
        }
    }
    __syncthreads();

    const int lane = t & 31;
    const int w = t >> 5;
    const int wm = w & 3, wn = w >> 2;
    const int grp = lane >> 2, qid = lane & 3;

    unsigned as_base = (unsigned)__cvta_generic_to_shared(&Abf[0][0]);
    unsigned bs_base = (unsigned)__cvta_generic_to_shared(&Bbf[0][0]);
    unsigned a_addr = as_base + (((wm * 32 + (lane & 15)) * 72 + ((lane >> 4) << 3)) << 1);
    unsigned b_addr = bs_base + (((wn * 64 + (lane & 7) + ((lane & 16) >> 1)) * 72 + (lane & 8)) << 1);

    float d[2][8][4];
#pragma unroll
    for (int mt = 0; mt < 2; mt++)
#pragma unroll
        for (int nt = 0; nt < 8; nt++)
#pragma unroll
            for (int e = 0; e < 4; e++) d[mt][nt][e] = 0.f;

#pragma unroll
    for (int kk = 0; kk < 4; kk++) {
        unsigned a[2][4];
        ldmx4(a[0][0], a[0][1], a[0][2], a[0][3], a_addr + kk * 32);
        ldmx4(a[1][0], a[1][1], a[1][2], a[1][3], a_addr + 2304 + kk * 32);
#pragma unroll
        for (int np = 0; np < 4; np++) {
            unsigned b0, b1, b2, b3;
            ldmx4(b0, b1, b2, b3, b_addr + np * 2304 + kk * 32);
            mma_bf16(d[0][2 * np],     a[0][0], a[0][1], a[0][2], a[0][3], b0, b1);
            mma_bf16(d[0][2 * np + 1], a[0][0], a[0][1], a[0][2], a[0][3], b2, b3);
            mma_bf16(d[1][2 * np],     a[1][0], a[1][1], a[1][2], a[1][3], b0, b1);
            mma_bf16(d[1][2 * np + 1], a[1][0], a[1][1], a[1][2], a[1][3], b2, b3);
        }
    }
    __syncthreads();   // ldmx4 done -> safe to overlay Gt on Abf/Bbf

    __nv_bfloat16 (*Gt)[136] = reinterpret_cast<__nv_bfloat16(*)[136]>(sbuf);
#pragma unroll
    for (int nt = 0; nt < 8; nt++) {
        int jl0 = wn * 64 + nt * 8 + qid * 2;
        float A1j[2] = {cA1j[jl0], cA1j[jl0 + 1]};
        float A2j[2] = {cA2j[jl0], cA2j[jl0 + 1]};
        float A3j[2] = {cA3j[jl0], cA3j[jl0 + 1]};
        float Vj[2]  = {cVj[jl0],  cVj[jl0 + 1]};
#pragma unroll
        for (int mh = 0; mh < 4; mh++) {
            int mt = mh >> 1, hh = mh & 1;
            int il = wm * 32 + mt * 16 + grp + hh * 8;
            int gi = ib + il;
            float A1 = cA1i[il], A2 = cA2i[il], A3 = cA3i[il], Vv = cVi[il];
            float hv[2];
#pragma unroll
            for (int c = 0; c < 2; c++) {
                int gj = jb + jl0 + c;
                float c0 = d[mt][nt][hh * 2 + c];
                float h;
                if (diag_tile && gi < gj) {
                    h = 0.f;
                } else if (gi == gj) {
                    c0 = Vv;                           // exact fp32 diagonal
                    float cc2 = c0 * c0;
                    h = 0.5f * (A1 * A1j[c] * c0
                              + 2.f * A2 * A2j[c] * cc2
                              + A3 * A3j[c] * (6.f * cc2 * c0 + 9.f * Vv * Vj[c] * c0));
                } else {
                    float cc2 = c0 * c0;
                    h = A1 * A1j[c] * c0
                      + 2.f * A2 * A2j[c] * cc2
                      + A3 * A3j[c] * (6.f * cc2 * c0 + 9.f * Vv * Vj[c] * c0);
                }
                hv[c] = h;
            }
            *reinterpret_cast<__nv_bfloat162*>(&Gt[il][jl0]) =
                __floats2bfloat162_rn(hv[0], hv[1]);
        }
    }
    __syncthreads();

#pragma unroll
    for (int q = 0; q < 8; q++) {
        int f = t + q * 256;
        int row = f >> 4, c16 = f & 15;
        *reinterpret_cast<uint4*>(
            &g_Hbf[((size_t)b * 512 + ib + row) * 512 + jb + c16 * 8]) =
            *reinterpret_cast<const uint4*>(&Gt[row][c16 * 8]);
    }
}

// ------------------- diag + probs: bf16 MMA, 4x2 warp split, 1 sync/chunk ------
// dynamic smem: 2 stages x [A 18432 | B 18432] = 73728 B.
// Warp (wm2, wj): o rows [wm2*32,+32), j cols [wj*64,+64).
// Pipeline: wait_group 0 -> barrier -> stage(c+1) -> compute(c).  The single
// barrier guarantees chunk c data visible AND chunk c-1 consumed by all before
// its buffer is overwritten.  Fold uses bf16 w41 (halves epilogue L2 traffic).
__global__ __launch_bounds__(256, 2) void bilinear_probs_bf16(
    float* __restrict__ probs_out)
{
    extern __shared__ __align__(16) char dsm[];
    __shared__ float red[2][128];

    const int t = threadIdx.x;
    const int lane = t & 31;
    const int w = t >> 5;
    const int wm2 = w & 3;             // o-group (32 rows)
    const int wj  = w >> 2;            // j-half (64 cols)
    const int ob = blockIdx.x * 128;
    const int b  = blockIdx.y;
    const __nv_bfloat16* Hb = g_Hbf + ((size_t)b << 18);

    const int grp = lane >> 2;
    const int qid = lane & 3;

    unsigned smem_base = (unsigned)__cvta_generic_to_shared(dsm);
    unsigned a_frag = smem_base +
        (((wm2 * 32 + (lane & 15)) * 72 + ((lane >> 4) << 3)) << 1);
    unsigned b_frag = smem_base + 18432u +
        (((wj * 64 + (lane & 7) + ((lane & 16) >> 1)) * 72 + (lane & 8)) << 1);

    float s[2][2];                     // partials: [mt][half-row]
    s[0][0] = s[0][1] = s[1][0] = s[1][1] = 0.f;

    for (int jt = 0; jt < 4; jt++) {
        const int jb = jt * 128;
        const int nch = 2 * (jt + 1);  // 64-wide k-chunks (triangular)
        float d[2][8][4];
#pragma unroll
        for (int mt = 0; mt < 2; mt++)
#pragma unroll
            for (int nt = 0; nt < 8; nt++)
#pragma unroll
                for (int c = 0; c < 4; c++) d[mt][nt][c] = 0.f;

        auto stage = [&](int kc, int buf) {
            unsigned off = buf ? 36864u : 0u;
#pragma unroll
            for (int q = 0; q < 4; q++) {
                int f = t + q * 256;
                int row = f >> 3, g = f & 7;
                int og = ob + row;
                const __nv_bfloat16* asrc =
                    g_w41bf + (size_t)(og < 784 ? og : 783) * 512 + kc + g * 8;
                unsigned adst = smem_base + off + ((unsigned)(row * 72 + g * 8) << 1);
                unsigned nbytes = (og < 784) ? 16u : 0u;   // zero-fill OOB rows
                asm volatile("cp.async.cg.shared.global [%0], [%1], 16, %2;"
                             :: "r"(adst), "l"(asrc), "r"(nbytes));
                const __nv_bfloat16* bsrc = Hb + (size_t)(jb + row) * 512 + kc + g * 8;
                unsigned bdst = smem_base + 18432u + off +
                                ((unsigned)(row * 72 + g * 8) << 1);
                asm volatile("cp.async.cg.shared.global [%0], [%1], 16;"
                             :: "r"(bdst), "l"(bsrc));
            }
            asm volatile("cp.async.commit_group;");
        };

        stage(0, 0);
        for (int c = 0; c < nch; c++) {
            asm volatile("cp.async.wait_group 0;" ::: "memory");
            __syncthreads();
            if (c + 1 < nch) stage((c + 1) * 64, (c + 1) & 1);

            unsigned sel = (c & 1) ? 36864u : 0u;
#pragma unroll
            for (int kk = 0; kk < 4; kk++) {
                unsigned a[2][4];
                ldmx4(a[0][0], a[0][1], a[0][2], a[0][3], a_frag + sel + kk * 32);
                ldmx4(a[1][0], a[1][1], a[1][2], a[1][3], a_frag + sel + 2304 + kk * 32);
#pragma unroll
                for (int np = 0; np < 4; np++) {
                    unsigned b0, b1, b2, b3;
                    ldmx4(b0, b1, b2, b3, b_frag + sel + np * 2304 + kk * 32);
                    mma_bf16(d[0][2 * np],     a[0][0], a[0][1], a[0][2], a[0][3], b0, b1);
                    mma_bf16(d[0][2 * np + 1], a[0][0], a[0][1], a[0][2], a[0][3], b2, b3);
                    mma_bf16(d[1][2 * np],     a[1][0], a[1][1], a[1][2], a[1][3], b0, b1);
                    mma_bf16(d[1][2 * np + 1], a[1][0], a[1][1], a[1][2], a[1][3], b2, b3);
                }
            }
        }

        // fold bf16 w41[o, j] for this warp's 64-wide j-slice
#pragma unroll
        for (int mt = 0; mt < 2; mt++) {
            int o0 = ob + wm2 * 32 + mt * 16 + grp;
#pragma unroll
            for (int hh = 0; hh < 2; hh++) {
                int og = o0 + hh * 8;
                if (og < 784) {
                    float acc = 0.f;
#pragma unroll
                    for (int nt = 0; nt < 8; nt++) {
                        int j0 = jb + wj * 64 + nt * 8 + qid * 2;
                        float2 f = __bfloat1622float2(
                            *reinterpret_cast<const __nv_bfloat162*>(
                                g_w41bf + (size_t)og * 512 + j0));
                        acc += d[mt][nt][hh * 2] * f.x + d[mt][nt][hh * 2 + 1] * f.y;
                    }
                    s[mt][hh] += acc;
                }
            }
        }
    }

    // qid-shuffle reduce, then cross-warp (wj) reduce via smem
#pragma unroll
    for (int mt = 0; mt < 2; mt++)
#pragma unroll
        for (int hh = 0; hh < 2; hh++) {
            s[mt][hh] += __shfl_xor_sync(0xffffffff, s[mt][hh], 1);
            s[mt][hh] += __shfl_xor_sync(0xffffffff, s[mt][hh], 2);
        }
    if (qid == 0) {
#pragma unroll
        for (int mt = 0; mt < 2; mt++)
#pragma unroll
            for (int hh = 0; hh < 2; hh++)
                red[wj][wm2 * 32 + mt * 16 + grp + hh * 8] = s[mt][hh];
    }
    __syncthreads();

    if (t < 128) {
        int og = ob + t;
        if (og < 784) {
            float vv = fmaxf(2.f * (red[0][t] + red[1][t]), EPSC);
            float m = g_m41[b * 784 + og];
            float sacc = 0.f;
#pragma unroll
            for (int g = 0; g < 5; g++) {
                float gam = GSU[g];
                float cg = 1.0f / (2.0f * gam * gam);
                float ivh = vv + cg;
                sacc += WSU[g] * 0.5f * (1.0f + erff(m / sqrtf(2.0f * ivh)));
            }
            probs_out[b * 784 + og] = sacc * 0.1f;
        }
    }
}

// ------------------- launcher --------------------------------------------------
extern "C" void kernel_launch(void* const* d_in, const int* in_sizes, int n_in,
                              void* d_out, int out_size)
{
    const float* x   = (const float*)d_in[0];
    const float* w1  = (const float*)d_in[1];
    const float* b1  = (const float*)d_in[2];
    const float* w21 = (const float*)d_in[3];
    const float* b21 = (const float*)d_in[4];
    const float* w22 = (const float*)d_in[5];
    const float* b22 = (const float*)d_in[6];
    const float* w3  = (const float*)d_in[7];
    const float* b3  = (const float*)d_in[8];
    const float* w41 = (const float*)d_in[9];
    const float* b41 = (const float*)d_in[10];
    float* out = (float*)d_out;

    float* h1;
    cudaGetSymbolAddress((void**)&h1, g_h1);

    const int BIL_SMEM = 73728;        // two stages (R13 geometry)
    cudaFuncSetAttribute(bilinear_probs_bf16,
                         cudaFuncAttributeMaxDynamicSharedMemorySize, BIL_SMEM);

    // h1 GEMM (128 blocks, 8x4 warp tiles) + w41 bf16 conversion (784 blocks)
    h1_conv<<<912, 256>>>(x, w1, b1, w41);
    // z GEMMs + tanh moment coefficients, one launch (z_mean/z_logvar -> out)
    zmoments<<<128, 256>>>(h1, w21, b21, w22, b22, w3, b3, out);
    // G build via bf16 MMA (640 blocks) + m41 GEMM (196 blocks, 8x4 tiles)
    build_H_m41<<<836, 256>>>(w3, w41, b41);
    // diag of cov41 (4x2 warp split, 1 sync/chunk cp.async) + fused probs
    bilinear_probs_bf16<<<dim3(7, 64), 256, BIL_SMEM>>>(out + 2 * 64 * 64);
}

// round 17
// speedup vs baseline: 1.0763x; 1.0002x over previous
#include <cuda_runtime.h>
#include <cuda_bf16.h>
#include <math.h>

#define EPSC 1e-6f
#define INV_SQRT_2PI 0.3989422804014327f

// deduped gamma tables (values within 4e-6 merged; weights preserve the mean)
__constant__ float GTU[5] = {0.715951561820333f, 1.039358092507381f, 0.948607106485449f,
                             0.484068718800797f, 1.446433070133343f};
__constant__ float WTU[5] = {4.f, 3.f, 1.f, 1.f, 1.f};
__constant__ float GSU[5] = {0.519483084417772f, 0.357944855434941f, 0.723301195883257f,
                             0.474918009444542f, 0.242049896394596f};
__constant__ float WSU[5] = {3.f, 4.f, 1.f, 1.f, 1.f};

// lower-triangle tile-pair tables for build_H (row tile >= col tile)
__constant__ int RT[10] = {0, 1, 1, 2, 2, 2, 3, 3, 3, 3};
__constant__ int CT[10] = {0, 0, 1, 0, 1, 2, 0, 1, 2, 3};

// ------------------- scratch (__device__ globals, no allocs) -------------------
__device__ float g_h1[64 * 512];
__device__ float g_zvar[64 * 64];
__device__ float g_a0[64 * 512];
__device__ float g_a1[64 * 512];
__device__ float g_a2[64 * 512];
__device__ float g_a3[64 * 512];
__device__ float g_v[64 * 512];
__device__ __nv_bfloat16 g_Hbf[(size_t)64 * 512 * 512];   // G = lower(H)+half-diag, bf16
__device__ __nv_bfloat16 g_w41bf[784 * 512];
__device__ float g_m41[64 * 784];

// ------------------- mma/ldmatrix helpers --------------------------------------
__device__ __forceinline__ void mma_bf16(float* d, unsigned a0, unsigned a1,
                                         unsigned a2, unsigned a3,
                                         unsigned b0, unsigned b1) {
    asm volatile(
        "mma.sync.aligned.m16n8k16.row.col.f32.bf16.bf16.f32 "
        "{%0,%1,%2,%3}, {%4,%5,%6,%7}, {%8,%9}, {%0,%1,%2,%3};"
        : "+f"(d[0]), "+f"(d[1]), "+f"(d[2]), "+f"(d[3])
        : "r"(a0), "r"(a1), "r"(a2), "r"(a3), "r"(b0), "r"(b1));
}
__device__ __forceinline__ void ldmx4(unsigned& r0, unsigned& r1, unsigned& r2,
                                      unsigned& r3, unsigned addr) {
    asm volatile(
        "ldmatrix.sync.aligned.m8n8.x4.shared.b16 {%0,%1,%2,%3}, [%4];"
        : "=r"(r0), "=r"(r1), "=r"(r2), "=r"(r3) : "r"(addr));
}

// ------------------- 8x4 warp-tile fp32 GEMM body ------------------------------
template <bool TANH>
__device__ __forceinline__ void warp_gemm_8x4(
    const float* __restrict__ A, int lda,
    const float* __restrict__ B, int ldb,
    const float* __restrict__ bias,
    float* __restrict__ out, int ldo,
    int m0, int n0, int K4, int lane)
{
    float s[8][4];
#pragma unroll
    for (int r = 0; r < 8; r++)
#pragma unroll
        for (int c = 0; c < 4; c++) s[r][c] = 0.f;

    const float4* ap[8];
#pragma unroll
    for (int r = 0; r < 8; r++)
        ap[r] = reinterpret_cast<const float4*>(A + (size_t)(m0 + r) * lda);
    const float4* bp[4];
#pragma unroll
    for (int c = 0; c < 4; c++)
        bp[c] = reinterpret_cast<const float4*>(B + (size_t)(n0 + c) * ldb);

    for (int i = lane; i < K4; i += 32) {
        float4 w[4];
#pragma unroll
        for (int c = 0; c < 4; c++) w[c] = bp[c][i];
#pragma unroll
        for (int r = 0; r < 8; r++) {
            float4 a = ap[r][i];
#pragma unroll
            for (int c = 0; c < 4; c++)
                s[r][c] += a.x * w[c].x + a.y * w[c].y + a.z * w[c].z + a.w * w[c].w;
        }
    }
#pragma unroll
    for (int off = 16; off; off >>= 1)
#pragma unroll
        for (int r = 0; r < 8; r++)
#pragma unroll
            for (int c = 0; c < 4; c++)
                s[r][c] += __shfl_xor_sync(0xffffffff, s[r][c], off);

    if (lane < 8) {
        float4 bb = *reinterpret_cast<const float4*>(bias + n0);
        float v0 = 0.f, v1 = 0.f, v2 = 0.f, v3 = 0.f;
#pragma unroll
        for (int r = 0; r < 8; r++)
            if (lane == r) { v0 = s[r][0]; v1 = s[r][1]; v2 = s[r][2]; v3 = s[r][3]; }
        float4 o;
        if (TANH) {
            o.x = tanhf(v0 + bb.x); o.y = tanhf(v1 + bb.y);
            o.z = tanhf(v2 + bb.z); o.w = tanhf(v3 + bb.w);
        } else {
            o.x = v0 + bb.x; o.y = v1 + bb.y; o.z = v2 + bb.z; o.w = v3 + bb.w;
        }
        *reinterpret_cast<float4*>(out + (size_t)(m0 + lane) * ldo + n0) = o;
    }
}

// ------------------- h1 GEMM (8x4 tiles) + w41 bf16 conversion -----------------
__global__ __launch_bounds__(256) void h1_conv(
    const float* __restrict__ x, const float* __restrict__ w1,
    const float* __restrict__ b1, const float* __restrict__ w41)
{
    if (blockIdx.x >= 128) {           // w41 -> bf16, 784 blocks
        int i = (blockIdx.x - 128) * 256 + threadIdx.x;
        float2 v = reinterpret_cast<const float2*>(w41)[i];
        reinterpret_cast<__nv_bfloat162*>(g_w41bf)[i] = __floats2bfloat162_rn(v.x, v.y);
        return;
    }
    const int wid  = (blockIdx.x * 256 + threadIdx.x) >> 5;
    const int lane = threadIdx.x & 31;
    const int tm = wid >> 7, tn = wid & 127;
    warp_gemm_8x4<true>(x, 784, w1, 784, b1, g_h1, 512,
                        tm * 8, tn * 4, 196, lane);
}

// ------------------- zmoments: z GEMMs + tanh moment coefficients --------------
__global__ __launch_bounds__(256) void zmoments(
    const float* __restrict__ h1,
    const float* __restrict__ w21, const float* __restrict__ b21,
    const float* __restrict__ w22, const float* __restrict__ b22,
    const float* __restrict__ w3, const float* __restrict__ b3,
    float* __restrict__ out)
{
    __shared__ float hs[512];
    __shared__ float zm[64], zr[64];
    const int t = threadIdx.x;
    const int b = blockIdx.x >> 1;
    const int half = blockIdx.x & 1;
    const int lane = t & 31, w = t >> 5;

    if (t < 128)
        *reinterpret_cast<float4*>(&hs[t * 4]) =
            *reinterpret_cast<const float4*>(h1 + (size_t)b * 512 + t * 4);
    __syncthreads();

#pragma unroll
    for (int u = 0; u < 8; u++) {
        int n = w * 8 + u;
        const float4* wmp = reinterpret_cast<const float4*>(w21 + (size_t)n * 512);
        const float4* wlp = reinterpret_cast<const float4*>(w22 + (size_t)n * 512);
        float sm = 0.f, sl = 0.f;
#pragma unroll
        for (int i = lane; i < 128; i += 32) {
            float4 hv = *reinterpret_cast<const float4*>(&hs[i * 4]);
            float4 a = wmp[i], bb2 = wlp[i];
            sm += hv.x * a.x + hv.y * a.y + hv.z * a.z + hv.w * a.w;
            sl += hv.x * bb2.x + hv.y * bb2.y + hv.z * bb2.z + hv.w * bb2.w;
        }
#pragma unroll
        for (int off = 16; off; off >>= 1) {
            sm += __shfl_xor_sync(0xffffffff, sm, off);
            sl += __shfl_xor_sync(0xffffffff, sl, off);
        }
        if (lane == 0) {
            sm += b21[n]; sl += b22[n];
            float ev = expf(sl);
            zm[n] = sm; zr[n] = ev;
            if (half == 0) {
                out[b * 64 + n] = sm;                  // z_mean
            } else {
                out[64 * 64 + b * 64 + n] = sl;        // z_logvar
                g_zvar[b * 64 + n] = ev;
            }
        }
    }
    __syncthreads();

    const int i = (half << 8) + t;
    const float4* wr = reinterpret_cast<const float4*>(w3 + (size_t)i * 64);
    float v = 0.f, m = b3[i];
#pragma unroll
    for (int q = 0; q < 16; q++) {
        float4 wv = wr[q];
        v += wv.x * wv.x * zr[q * 4 + 0] + wv.y * wv.y * zr[q * 4 + 1]
           + wv.z * wv.z * zr[q * 4 + 2] + wv.w * wv.w * zr[q * 4 + 3];
        m += wv.x * zm[q * 4 + 0] + wv.y * zm[q * 4 + 1]
           + wv.z * zm[q * 4 + 2] + wv.w * zm[q * 4 + 3];
    }
    v = fmaxf(v, EPSC);

    float s0 = 0.f, s1 = 0.f, s2 = 0.f, s3 = 0.f;
#pragma unroll
    for (int g = 0; g < 5; g++) {
        float gam = GTU[g], wgt = WTU[g];
        float cg = 1.0f / (2.0f * gam * gam);
        float ivh = v + cg;
        float sq = sqrtf(ivh);
        float mu = m / sq;
        float Bv = expf(-0.5f * mu * mu) * INV_SQRT_2PI / sq;
        float Cv = 0.5f * (1.0f + erff(mu * 0.70710678118654752f));
        s0 += wgt * (2.f * Cv - 1.f);
        s1 += wgt * (2.f * Bv);
        s2 += wgt * (-Bv * m / ivh);
        s3 += wgt * ((1.f / 3.f) * Bv * (m * m - ivh) / (ivh * ivh));
    }
    int idx = b * 512 + i;
    g_a0[idx] = s0 * 0.1f;
    g_a1[idx] = s1 * 0.1f;
    g_a2[idx] = s2 * 0.1f;
    g_a3[idx] = s3 * 0.1f;
    g_v[idx]  = v;
}

// ------------------- build G (bf16 MMA) + m41 GEMM (merged launch) -------------
__global__ __launch_bounds__(256, 2) void build_H_m41(
    const float* __restrict__ w3, const float* __restrict__ w41,
    const float* __restrict__ b41)
{
    __shared__ __align__(16) char sbuf[36864];   // Abf+Bbf during MMA; Gt after
    __shared__ float zrs[64];
    __shared__ float cA1i[128], cA2i[128], cA3i[128], cVi[128];
    __shared__ float cA1j[128], cA2j[128], cA3j[128], cVj[128];

    const int t = threadIdx.x;
    if (blockIdx.x >= 640) {            // ---- m41 8x4 warp GEMM ----
        const int wid  = ((blockIdx.x - 640) * 256 + t) >> 5;
        const int lane = t & 31;
        const int tm = wid / 196, tn = wid - tm * 196;
        warp_gemm_8x4<false>(g_a0, 512, w41, 512, b41, g_m41, 784,
                             tm * 8, tn * 4, 128, lane);
        return;
    }

    __nv_bfloat16 (*Abf)[72] = reinterpret_cast<__nv_bfloat16(*)[72]>(sbuf);
    __nv_bfloat16 (*Bbf)[72] = reinterpret_cast<__nv_bfloat16(*)[72]>(sbuf + 18432);

    const int pair = blockIdx.x % 10;
    const int b = blockIdx.x / 10;
    const int ib = RT[pair] * 128, jb = CT[pair] * 128;
    const bool diag_tile = (ib == jb);

    if (t < 64) zrs[t] = g_zvar[b * 64 + t];
    {   // coalesced coefficient staging
        int side = t >> 7;
        int r = t & 127;
        int gg = b * 512 + (side ? jb : ib) + r;
        if (side == 0) {
            cA1i[r] = g_a1[gg]; cA2i[r] = g_a2[gg];
            cA3i[r] = g_a3[gg]; cVi[r]  = g_v[gg];
        } else {
            cA1j[r] = g_a1[gg]; cA2j[r] = g_a2[gg];
            cA3j[r] = g_a3[gg]; cVj[r]  = g_v[gg];
        }
    }
    __syncthreads();

    {   // stage W3 tiles (bf16), B side z-scaled
        int row = t >> 1, base = (t & 1) * 8;
        const float4* wa = reinterpret_cast<const float4*>(w3 + (size_t)(ib + row) * 64);
        const float4* wb = reinterpret_cast<const float4*>(w3 + (size_t)(jb + row) * 64);
#pragma unroll
        for (int q = 0; q < 8; q++) {
            int c4 = base + q;
            float4 va = wa[c4];
            *reinterpret_cast<__nv_bfloat162*>(&Abf[row][c4 * 4])     = __floats2bfloat162_rn(va.x, va.y);
            *reinterpret_cast<__nv_bfloat162*>(&Abf[row][c4 * 4 + 2]) = __floats2bfloat162_rn(va.z, va.w);
            float4 vb = wb[c4];
            *reinterpret_cast<__nv_bfloat162*>(&Bbf[row][c4 * 4])     =
                __floats2bfloat162_rn(vb.x * zrs[c4 * 4 + 0], vb.y * zrs[c4 * 4 + 1]);
            *reinterpret_cast<__nv_bfloat162*>(&Bbf[row][c4 * 4 + 2]) =
                __floats2bfloat162_rn(vb.z * zrs[c4 * 4 + 2], vb.w * zrs[c4 * 4 + 3]);
        }
    }
    __syncthreads();

    const int lane = t & 31;
    const int w = t >> 5;
    const int wm = w & 3, wn = w >> 2;
    const int grp = lane >> 2, qid = lane & 3;

    unsigned as_base = (unsigned)__cvta_generic_to_shared(&Abf[0][0]);
    unsigned bs_base = (unsigned)__cvta_generic_to_shared(&Bbf[0][0]);
    unsigned a_addr = as_base + (((wm * 32 + (lane & 15)) * 72 + ((lane >> 4) << 3)) << 1);
    unsigned b_addr = bs_base + (((wn * 64 + (lane & 7) + ((lane & 16) >> 1)) * 72 + (lane & 8)) << 1);

    float d[2][8][4];
#pragma unroll
    for (int mt = 0; mt < 2; mt++)
#pragma unroll
        for (int nt = 0; nt < 8; nt++)
#pragma unroll
            for (int e = 0; e < 4; e++) d[mt][nt][e] = 0.f;

#pragma unroll
    for (int kk = 0; kk < 4; kk++) {
        unsigned a[2][4];
        ldmx4(a[0][0], a[0][1], a[0][2], a[0][3], a_addr + kk * 32);
        ldmx4(a[1][0], a[1][1], a[1][2], a[1][3], a_addr + 2304 + kk * 32);
#pragma unroll
        for (int np = 0; np < 4; np++) {
            unsigned b0, b1, b2, b3;
            ldmx4(b0, b1, b2, b3, b_addr + np * 2304 + kk * 32);
            mma_bf16(d[0][2 * np],     a[0][0], a[0][1], a[0][2], a[0][3], b0, b1);
            mma_bf16(d[0][2 * np + 1], a[0][0], a[0][1], a[0][2], a[0][3], b2, b3);
            mma_bf16(d[1][2 * np],     a[1][0], a[1][1], a[1][2], a[1][3], b0, b1);
            mma_bf16(d[1][2 * np + 1], a[1][0], a[1][1], a[1][2], a[1][3], b2, b3);
        }
    }
    __syncthreads();   // ldmx4 done -> safe to overlay Gt on Abf/Bbf

    __nv_bfloat16 (*Gt)[136] = reinterpret_cast<__nv_bfloat16(*)[136]>(sbuf);
#pragma unroll
    for (int nt = 0; nt < 8; nt++) {
        int jl0 = wn * 64 + nt * 8 + qid * 2;
        float A1j[2] = {cA1j[jl0], cA1j[jl0 + 1]};
        float A2j[2] = {cA2j[jl0], cA2j[jl0 + 1]};
        float A3j[2] = {cA3j[jl0], cA3j[jl0 + 1]};
        float Vj[2]  = {cVj[jl0],  cVj[jl0 + 1]};
#pragma unroll
        for (int mh = 0; mh < 4; mh++) {
            int mt = mh >> 1, hh = mh & 1;
            int il = wm * 32 + mt * 16 + grp + hh * 8;
            int gi = ib + il;
            float A1 = cA1i[il], A2 = cA2i[il], A3 = cA3i[il], Vv = cVi[il];
            float hv[2];
#pragma unroll
            for (int c = 0; c < 2; c++) {
                int gj = jb + jl0 + c;
                float c0 = d[mt][nt][hh * 2 + c];
                float h;
                if (diag_tile && gi < gj) {
                    h = 0.f;
                } else if (gi == gj) {
                    c0 = Vv;                           // exact fp32 diagonal
                    float cc2 = c0 * c0;
                    h = 0.5f * (A1 * A1j[c] * c0
                              + 2.f * A2 * A2j[c] * cc2
                              + A3 * A3j[c] * (6.f * cc2 * c0 + 9.f * Vv * Vj[c] * c0));
                } else {
                    float cc2 = c0 * c0;
                    h = A1 * A1j[c] * c0
                      + 2.f * A2 * A2j[c] * cc2
                      + A3 * A3j[c] * (6.f * cc2 * c0 + 9.f * Vv * Vj[c] * c0);
                }
                hv[c] = h;
            }
            *reinterpret_cast<__nv_bfloat162*>(&Gt[il][jl0]) =
                __floats2bfloat162_rn(hv[0], hv[1]);
        }
    }
    __syncthreads();

#pragma unroll
    for (int q = 0; q < 8; q++) {
        int f = t + q * 256;
        int row = f >> 4, c16 = f & 15;
        *reinterpret_cast<uint4*>(
            &g_Hbf[((size_t)b * 512 + ib + row) * 512 + jb + c16 * 8]) =
            *reinterpret_cast<const uint4*>(&Gt[row][c16 * 8]);
    }
}

// ------------------- diag + probs: bf16 MMA, 4x2 warp split, 1 sync/chunk ------
// dynamic smem: 2 stages x [A 18432 | B 18432] = 73728 B.
// Warp (wm2, wj): o rows [wm2*32,+32), j cols [wj*64,+64).
// Pipeline: wait_group 0 -> barrier -> stage(c+1) -> compute(c).  The single
// barrier guarantees chunk c data visible AND chunk c-1 consumed by all before
// its buffer is overwritten.  Fold uses bf16 w41 (halves epilogue L2 traffic).
__global__ __launch_bounds__(256, 2) void bilinear_probs_bf16(
    float* __restrict__ probs_out)
{
    extern __shared__ __align__(16) char dsm[];
    __shared__ float red[2][128];

    const int t = threadIdx.x;
    const int lane = t & 31;
    const int w = t >> 5;
    const int wm2 = w & 3;             // o-group (32 rows)
    const int wj  = w >> 2;            // j-half (64 cols)
    const int ob = blockIdx.x * 128;
    const int b  = blockIdx.y;
    const __nv_bfloat16* Hb = g_Hbf + ((size_t)b << 18);

    const int grp = lane >> 2;
    const int qid = lane & 3;

    unsigned smem_base = (unsigned)__cvta_generic_to_shared(dsm);
    unsigned a_frag = smem_base +
        (((wm2 * 32 + (lane & 15)) * 72 + ((lane >> 4) << 3)) << 1);
    unsigned b_frag = smem_base + 18432u +
        (((wj * 64 + (lane & 7) + ((lane & 16) >> 1)) * 72 + (lane & 8)) << 1);

    float s[2][2];                     // partials: [mt][half-row]
    s[0][0] = s[0][1] = s[1][0] = s[1][1] = 0.f;

    for (int jt = 0; jt < 4; jt++) {
        const int jb = jt * 128;
        const int nch = 2 * (jt + 1);  // 64-wide k-chunks (triangular)
        float d[2][8][4];
#pragma unroll
        for (int mt = 0; mt < 2; mt++)
#pragma unroll
            for (int nt = 0; nt < 8; nt++)
#pragma unroll
                for (int c = 0; c < 4; c++) d[mt][nt][c] = 0.f;

        auto stage = [&](int kc, int buf) {
            unsigned off = buf ? 36864u : 0u;
#pragma unroll
            for (int q = 0; q < 4; q++) {
                int f = t + q * 256;
                int row = f >> 3, g = f & 7;
                int og = ob + row;
                const __nv_bfloat16* asrc =
                    g_w41bf + (size_t)(og < 784 ? og : 783) * 512 + kc + g * 8;
                unsigned adst = smem_base + off + ((unsigned)(row * 72 + g * 8) << 1);
                unsigned nbytes = (og < 784) ? 16u : 0u;   // zero-fill OOB rows
                asm volatile("cp.async.cg.shared.global [%0], [%1], 16, %2;"
                             :: "r"(adst), "l"(asrc), "r"(nbytes));
                const __nv_bfloat16* bsrc = Hb + (size_t)(jb + row) * 512 + kc + g * 8;
                unsigned bdst = smem_base + 18432u + off +
                                ((unsigned)(row * 72 + g * 8) << 1);
                asm volatile("cp.async.cg.shared.global [%0], [%1], 16;"
                             :: "r"(bdst), "l"(bsrc));
            }
            asm volatile("cp.async.commit_group;");
        };

        stage(0, 0);
        for (int c = 0; c < nch; c++) {
            asm volatile("cp.async.wait_group 0;" ::: "memory");
            __syncthreads();
            if (c + 1 < nch) stage((c + 1) * 64, (c + 1) & 1);

            unsigned sel = (c & 1) ? 36864u : 0u;
#pragma unroll
            for (int kk = 0; kk < 4; kk++) {
                unsigned a[2][4];
                ldmx4(a[0][0], a[0][1], a[0][2], a[0][3], a_frag + sel + kk * 32);
                ldmx4(a[1][0], a[1][1], a[1][2], a[1][3], a_frag + sel + 2304 + kk * 32);
#pragma unroll
                for (int np = 0; np < 4; np++) {
                    unsigned b0, b1, b2, b3;
                    ldmx4(b0, b1, b2, b3, b_frag + sel + np * 2304 + kk * 32);
                    mma_bf16(d[0][2 * np],     a[0][0], a[0][1], a[0][2], a[0][3], b0, b1);
                    mma_bf16(d[0][2 * np + 1], a[0][0], a[0][1], a[0][2], a[0][3], b2, b3);
                    mma_bf16(d[1][2 * np],     a[1][0], a[1][1], a[1][2], a[1][3], b0, b1);
                    mma_bf16(d[1][2 * np + 1], a[1][0], a[1][1], a[1][2], a[1][3], b2, b3);
                }
            }
        }

        // fold bf16 w41[o, j] for this warp's 64-wide j-slice
#pragma unroll
        for (int mt = 0; mt < 2; mt++) {
            int o0 = ob + wm2 * 32 + mt * 16 + grp;
#pragma unroll
            for (int hh = 0; hh < 2; hh++) {
                int og = o0 + hh * 8;
                if (og < 784) {
                    float acc = 0.f;
#pragma unroll
                    for (int nt = 0; nt < 8; nt++) {
                        int j0 = jb + wj * 64 + nt * 8 + qid * 2;
                        float2 f = __bfloat1622float2(
                            *reinterpret_cast<const __nv_bfloat162*>(
                                g_w41bf + (size_t)og * 512 + j0));
                        acc += d[mt][nt][hh * 2] * f.x + d[mt][nt][hh * 2 + 1] * f.y;
                    }
                    s[mt][hh] += acc;
                }
            }
        }
    }

    // qid-shuffle reduce, then cross-warp (wj) reduce via smem
#pragma unroll
    for (int mt = 0; mt < 2; mt++)
#pragma unroll
        for (int hh = 0; hh < 2; hh++) {
            s[mt][hh] += __shfl_xor_sync(0xffffffff, s[mt][hh], 1);
            s[mt][hh] += __shfl_xor_sync(0xffffffff, s[mt][hh], 2);
        }
    if (qid == 0) {
#pragma unroll
        for (int mt = 0; mt < 2; mt++)
#pragma unroll
            for (int hh = 0; hh < 2; hh++)
                red[wj][wm2 * 32 + mt * 16 + grp + hh * 8] = s[mt][hh];
    }
    __syncthreads();

    if (t < 128) {
        int og = ob + t;
        if (og < 784) {
            float vv = fmaxf(2.f * (red[0][t] + red[1][t]), EPSC);
            float m = g_m41[b * 784 + og];
            float sacc = 0.f;
#pragma unroll
            for (int g = 0; g < 5; g++) {
                float gam = GSU[g];
                float cg = 1.0f / (2.0f * gam * gam);
                float ivh = vv + cg;
                sacc += WSU[g] * 0.5f * (1.0f + erff(m / sqrtf(2.0f * ivh)));
            }
            probs_out[b * 784 + og] = sacc * 0.1f;
        }
    }
}

// ------------------- launcher --------------------------------------------------
extern "C" void kernel_launch(void* const* d_in, const int* in_sizes, int n_in,
                              void* d_out, int out_size)
{
    const float* x   = (const float*)d_in[0];
    const float* w1  = (const float*)d_in[1];
    const float* b1  = (const float*)d_in[2];
    const float* w21 = (const float*)d_in[3];
    const float* b21 = (const float*)d_in[4];
    const float* w22 = (const float*)d_in[5];
    const float* b22 = (const float*)d_in[6];
    const float* w3  = (const float*)d_in[7];
    const float* b3  = (const float*)d_in[8];
    const float* w41 = (const float*)d_in[9];
    const float* b41 = (const float*)d_in[10];
    float* out = (float*)d_out;

    float* h1;
    cudaGetSymbolAddress((void**)&h1, g_h1);

    const int BIL_SMEM = 73728;        // two stages (R13 geometry)
    cudaFuncSetAttribute(bilinear_probs_bf16,
                         cudaFuncAttributeMaxDynamicSharedMemorySize, BIL_SMEM);

    // h1 GEMM (128 blocks, 8x4 warp tiles) + w41 bf16 conversion (784 blocks)
    h1_conv<<<912, 256>>>(x, w1, b1, w41);
    // z GEMMs + tanh moment coefficients, one launch (z_mean/z_logvar -> out)
    zmoments<<<128, 256>>>(h1, w21, b21, w22, b22, w3, b3, out);
    // G build via bf16 MMA (640 blocks) + m41 GEMM (196 blocks, 8x4 tiles)
    build_H_m41<<<836, 256>>>(w3, w41, b41);
    // diag of cov41 (4x2 warp split, 1 sync/chunk cp.async) + fused probs
    bilinear_probs_bf16<<<dim3(7, 64), 256, BIL_SMEM>>>(out + 2 * 64 * 64);
}